// round 3
// baseline (speedup 1.0000x reference)
#include <cuda_runtime.h>

#define CEPS 1e-3f

// scratch (allocation-free rule: __device__ globals)
__device__ float g_y0[100000 * 16];
__device__ float g_y1[100000 * 16];
__device__ float g_merged[200000 * 16];
__device__ float g_stats[64];   // [0:16) sum0, [16:32) sq0, [32:48) sum1, [48:64) sq1

typedef unsigned long long ull;

#define FMA2(d, a, b) asm("fma.rn.f32x2 %0, %1, %2, %0;" : "+l"(d) : "l"(a), "l"(b))

__device__ __forceinline__ ull pack2(float lo, float hi) {
    ull d;
    asm("mov.b64 %0, {%1, %2};" : "=l"(d) : "r"(__float_as_uint(lo)), "r"(__float_as_uint(hi)));
    return d;
}
__device__ __forceinline__ float f2lo(ull v) { return __uint_as_float((unsigned)v); }
__device__ __forceinline__ float f2hi(ull v) { return __uint_as_float((unsigned)(v >> 32)); }

// ---------------------------------------------------------------------------
// Submanifold 3x3x3 conv, f32x2 packed math.
// Block: 256 threads -> 256 rows x 16 out-ch. Thread: 4 rows x 4 ch.
// SMEM x layout: [row>>2][c][row&3], pitch 68 floats (conflict-free, 16B align).
// W staged per-k as duplicated pairs {w,w} so b64 FMA2 needs no packing.
// LAYER==1 applies BN0(affine from g_stats)+ReLU at gather (missing nbr -> 0).
// ---------------------------------------------------------------------------
#define CONV_SMEM (27648 + 34816 + 4096 + 256)

template <int LAYER>
__global__ __launch_bounds__(256) void conv_kernel(
    const float* __restrict__ x, const int* __restrict__ nbr,
    const float* __restrict__ W, float* __restrict__ y,
    const float* __restrict__ g, const float* __restrict__ b,
    int N, float invN)
{
    extern __shared__ char smem[];
    int*   snbr  = (int*)smem;                          // 256*27 ints
    float* xs    = (float*)(smem + 27648);              // 2 * 64*68 floats
    float* wk2   = (float*)(smem + 27648 + 34816);      // 2 * 512 floats
    float* saff  = (float*)(smem + 27648 + 34816 + 4096);
    float* sstat = saff + 32;

    int tid  = threadIdx.x;
    int row0 = blockIdx.x * 256;

    int lim = (N - row0) * 27;
    for (int i = tid; i < 256 * 27; i += 256)
        snbr[i] = (i < lim) ? nbr[row0 * 27 + i] : -1;
    if (tid < 32) sstat[tid] = 0.f;
    if (LAYER == 1 && tid < 16) {
        float mu  = g_stats[tid] * invN;
        float var = g_stats[16 + tid] * invN - mu * mu;
        float s   = g[tid] * rsqrtf(var + CEPS);
        saff[tid]      = s;
        saff[16 + tid] = b[tid] - mu * s;
    }
    __syncthreads();

    auto stage = [&](int k, int buf) {
        // W slice as duplicated pairs: wk2[c*32 + o*2 + h] = W[k][c][o]
        {
            float w0 = W[k * 256 + (tid >> 1)];
            wk2[buf * 512 + tid] = w0;
            float w1 = W[k * 256 + ((tid + 256) >> 1)];
            wk2[buf * 512 + tid + 256] = w1;
        }
        int id = snbr[tid * 27 + k];
        float4 v0, v1, v2, v3;
        if (id >= 0) {
            const float4* xp = (const float4*)(x + id * 16);
            v0 = xp[0]; v1 = xp[1]; v2 = xp[2]; v3 = xp[3];
            if (LAYER == 1) {
                v0.x = fmaxf(fmaf(v0.x, saff[0],  saff[16]),      0.f);
                v0.y = fmaxf(fmaf(v0.y, saff[1],  saff[17]),      0.f);
                v0.z = fmaxf(fmaf(v0.z, saff[2],  saff[18]),      0.f);
                v0.w = fmaxf(fmaf(v0.w, saff[3],  saff[19]),      0.f);
                v1.x = fmaxf(fmaf(v1.x, saff[4],  saff[20]),      0.f);
                v1.y = fmaxf(fmaf(v1.y, saff[5],  saff[21]),      0.f);
                v1.z = fmaxf(fmaf(v1.z, saff[6],  saff[22]),      0.f);
                v1.w = fmaxf(fmaf(v1.w, saff[7],  saff[23]),      0.f);
                v2.x = fmaxf(fmaf(v2.x, saff[8],  saff[24]),      0.f);
                v2.y = fmaxf(fmaf(v2.y, saff[9],  saff[25]),      0.f);
                v2.z = fmaxf(fmaf(v2.z, saff[10], saff[26]),      0.f);
                v2.w = fmaxf(fmaf(v2.w, saff[11], saff[27]),      0.f);
                v3.x = fmaxf(fmaf(v3.x, saff[12], saff[28]),      0.f);
                v3.y = fmaxf(fmaf(v3.y, saff[13], saff[29]),      0.f);
                v3.z = fmaxf(fmaf(v3.z, saff[14], saff[30]),      0.f);
                v3.w = fmaxf(fmaf(v3.w, saff[15], saff[31]),      0.f);
            }
        } else {
            v0 = v1 = v2 = v3 = make_float4(0.f, 0.f, 0.f, 0.f);
        }
        float* dst = xs + buf * 4352 + (tid >> 2) * 68 + (tid & 3);
        dst[0]  = v0.x; dst[4]  = v0.y; dst[8]  = v0.z; dst[12] = v0.w;
        dst[16] = v1.x; dst[20] = v1.y; dst[24] = v1.z; dst[28] = v1.w;
        dst[32] = v2.x; dst[36] = v2.y; dst[40] = v2.z; dst[44] = v2.w;
        dst[48] = v3.x; dst[52] = v3.y; dst[56] = v3.z; dst[60] = v3.w;
    };

    int tx = tid & 3;     // cout quad (channels tx*4 .. tx*4+3)
    int ty = tid >> 2;    // row quad  (rows ty*4 .. ty*4+3)

    ull acc[8];           // [pair p][cout o]: p=0 rows(0,1), p=1 rows(2,3)
#pragma unroll
    for (int i = 0; i < 8; i++) acc[i] = 0ull;

    stage(0, 0);
    __syncthreads();

    for (int k = 0; k < 27; k++) {
        int cur = k & 1;
        if (k < 26) stage(k + 1, cur ^ 1);

        const float* xb = xs + cur * 4352 + ty * 68;
        const float* wb = wk2 + cur * 512 + tx * 8;
#pragma unroll
        for (int c = 0; c < 16; c++) {
            ulonglong2 xv = *(const ulonglong2*)(xb + c * 4);     // rows 0-3 @ ch c
            ulonglong2 wA = *(const ulonglong2*)(wb + c * 32);    // {o0,o0},{o1,o1}
            ulonglong2 wB = *(const ulonglong2*)(wb + c * 32 + 4);// {o2,o2},{o3,o3}
            FMA2(acc[0], xv.x, wA.x); FMA2(acc[1], xv.x, wA.y);
            FMA2(acc[2], xv.x, wB.x); FMA2(acc[3], xv.x, wB.y);
            FMA2(acc[4], xv.y, wA.x); FMA2(acc[5], xv.y, wA.y);
            FMA2(acc[6], xv.y, wB.x); FMA2(acc[7], xv.y, wB.y);
        }
        __syncthreads();
    }

    // unpack: a[row i][cout o]
    float a[4][4];
#pragma unroll
    for (int o = 0; o < 4; o++) {
        a[0][o] = f2lo(acc[o]);     a[1][o] = f2hi(acc[o]);
        a[2][o] = f2lo(acc[4 + o]); a[3][o] = f2hi(acc[4 + o]);
    }

    float s[4] = {0.f, 0.f, 0.f, 0.f}, q[4] = {0.f, 0.f, 0.f, 0.f};
#pragma unroll
    for (int i = 0; i < 4; i++) {
        int r = row0 + ty * 4 + i;
        if (r < N) {
            *(float4*)(y + r * 16 + tx * 4) = make_float4(a[i][0], a[i][1], a[i][2], a[i][3]);
#pragma unroll
            for (int o = 0; o < 4; o++) { s[o] += a[i][o]; q[o] += a[i][o] * a[i][o]; }
        }
    }
    // warp reduce over the 8 row-quad lanes sharing a tx
#pragma unroll
    for (int off = 4; off < 32; off <<= 1) {
#pragma unroll
        for (int o = 0; o < 4; o++) {
            s[o] += __shfl_xor_sync(0xffffffffu, s[o], off);
            q[o] += __shfl_xor_sync(0xffffffffu, q[o], off);
        }
    }
    if ((tid & 31) < 4) {
#pragma unroll
        for (int o = 0; o < 4; o++) {
            atomicAdd(&sstat[tx * 4 + o], s[o]);
            atomicAdd(&sstat[16 + tx * 4 + o], q[o]);
        }
    }
    __syncthreads();
    if (tid < 32) atomicAdd(&g_stats[(LAYER == 0 ? 0 : 32) + tid], sstat[tid]);
}

// t2 = f2 @ Wobo + bobo, atomicAdd-scatter into merged (runs before convs)
__global__ __launch_bounds__(256) void fuse_t2_kernel(
    const float* __restrict__ f2, const float* __restrict__ Wobo,
    const float* __restrict__ bobo, const int* __restrict__ seg2, int N)
{
    __shared__ float Wo[256];
    __shared__ float sf[16 * 17];
    __shared__ float sb[16];
    int tid = threadIdx.x;
    Wo[tid] = Wobo[tid];
    if (tid < 16) sb[tid] = bobo[tid];
    int n0 = blockIdx.x * 16;
    if (tid < 64) {
        int r = tid >> 2, c4 = (tid & 3) * 4;
        float4 v = make_float4(0.f, 0.f, 0.f, 0.f);
        if (n0 + r < N) v = *(const float4*)(f2 + (n0 + r) * 16 + c4);
        sf[r * 17 + c4 + 0] = v.x; sf[r * 17 + c4 + 1] = v.y;
        sf[r * 17 + c4 + 2] = v.z; sf[r * 17 + c4 + 3] = v.w;
    }
    __syncthreads();
    int tx = tid & 15, ty = tid >> 4;
    int n = n0 + ty;
    if (n >= N) return;
    float acc = sb[tx];
#pragma unroll
    for (int c = 0; c < 16; c++)
        acc = fmaf(sf[ty * 17 + c], Wo[c * 16 + tx], acc);
    atomicAdd(&g_merged[seg2[n] * 16 + tx], acc);
}

// h = relu(bn1(y1)), atomicAdd-scatter into merged
__global__ __launch_bounds__(256) void fuse_h_kernel(
    const float* __restrict__ y1, const float* __restrict__ g1,
    const float* __restrict__ b1, const int* __restrict__ seg, int N, float invN)
{
    __shared__ float saff[32];
    int tid = threadIdx.x;
    if (tid < 16) {
        float mu  = g_stats[32 + tid] * invN;
        float var = g_stats[48 + tid] * invN - mu * mu;
        float s   = g1[tid] * rsqrtf(var + CEPS);
        saff[tid]      = s;
        saff[16 + tid] = b1[tid] - mu * s;
    }
    __syncthreads();
    int tx = tid & 15, ty = tid >> 4;
    int n = blockIdx.x * 16 + ty;
    if (n >= N) return;
    float h = fmaxf(fmaf(y1[n * 16 + tx], saff[tx], saff[16 + tx]), 0.f);
    atomicAdd(&g_merged[seg[n] * 16 + tx], h);
}

// out[u,:] = merged[u,:] @ Wf + bf.  Block: 32 rows x 128 cols, f32x2 math.
__global__ __launch_bounds__(256) void out_kernel(
    const float* __restrict__ Wf, const float* __restrict__ bf,
    float* __restrict__ out, int U)
{
    __shared__ float Wfs[2048];
    __shared__ float sx[32 * 16];
    int tid = threadIdx.x;
    for (int i = tid; i < 2048; i += 256) Wfs[i] = Wf[i];
    int u0 = blockIdx.x * 32;
    if (tid < 128) {
        int r = tid >> 2, c4 = (tid & 3) * 4;
        float4 v = make_float4(0.f, 0.f, 0.f, 0.f);
        if (u0 + r < U) v = *(const float4*)(g_merged + (u0 + r) * 16 + c4);
        *(float4*)(sx + r * 16 + c4) = v;
    }
    __syncthreads();

    int cx = tid & 31, ry = tid >> 5;    // cols cx*4..+3, rows ry*4..+3
    float4 bv = *(const float4*)(bf + cx * 4);
    ull b01 = pack2(bv.x, bv.y), b23 = pack2(bv.z, bv.w);
    ull acc[4][2];
#pragma unroll
    for (int i = 0; i < 4; i++) { acc[i][0] = b01; acc[i][1] = b23; }

#pragma unroll
    for (int c = 0; c < 16; c++) {
        ulonglong2 wv = *(const ulonglong2*)(Wfs + c * 128 + cx * 4);
#pragma unroll
        for (int i = 0; i < 4; i++) {
            float xv = sx[(ry * 4 + i) * 16 + c];
            ull xd = pack2(xv, xv);
            FMA2(acc[i][0], xd, wv.x);
            FMA2(acc[i][1], xd, wv.y);
        }
    }
#pragma unroll
    for (int i = 0; i < 4; i++) {
        int u = u0 + ry * 4 + i;
        if (u < U)
            *(float4*)(out + u * 128 + cx * 4) =
                make_float4(f2lo(acc[i][0]), f2hi(acc[i][0]),
                            f2lo(acc[i][1]), f2hi(acc[i][1]));
    }
}

extern "C" void kernel_launch(void* const* d_in, const int* in_sizes, int n_in,
                              void* d_out, int out_size)
{
    const float* vox  = (const float*)d_in[0];
    const float* f2   = (const float*)d_in[1];
    const float* W0   = (const float*)d_in[2];
    const float* g0   = (const float*)d_in[3];
    const float* b0   = (const float*)d_in[4];
    const float* W1   = (const float*)d_in[5];
    const float* g1   = (const float*)d_in[6];
    const float* b1   = (const float*)d_in[7];
    const float* Wobo = (const float*)d_in[8];
    const float* bobo = (const float*)d_in[9];
    const float* Wf   = (const float*)d_in[10];
    const float* bf   = (const float*)d_in[11];
    const int*   nbr  = (const int*)d_in[12];
    const int*   seg  = (const int*)d_in[13];

    int N = in_sizes[0] / 16;
    int U = out_size / 128;

    void *p_stats, *p_merged, *p_y0, *p_y1;
    cudaGetSymbolAddress(&p_stats,  g_stats);
    cudaGetSymbolAddress(&p_merged, g_merged);
    cudaGetSymbolAddress(&p_y0,     g_y0);
    cudaGetSymbolAddress(&p_y1,     g_y1);

    cudaFuncSetAttribute(conv_kernel<0>, cudaFuncAttributeMaxDynamicSharedMemorySize, CONV_SMEM);
    cudaFuncSetAttribute(conv_kernel<1>, cudaFuncAttributeMaxDynamicSharedMemorySize, CONV_SMEM);

    size_t mbytes = (size_t)U * 16 * sizeof(float);
    size_t mhalf  = (mbytes / 2) & ~(size_t)255;
    float invN = 1.0f / (float)N;
    int cblocks = (N + 255) / 256;

    cudaMemsetAsync(p_stats, 0, 64 * sizeof(float));                         // 0
    cudaMemsetAsync(p_merged, 0, mhalf);                                     // 1
    cudaMemsetAsync((char*)p_merged + mhalf, 0, mbytes - mhalf);             // 2
    fuse_t2_kernel<<<(N + 15) / 16, 256>>>(f2, Wobo, bobo, seg + N, N);      // 3
    conv_kernel<0><<<cblocks, 256, CONV_SMEM>>>(vox, nbr, W0, (float*)p_y0,
                                                g0, b0, N, invN);            // 4
    conv_kernel<1><<<cblocks, 256, CONV_SMEM>>>((const float*)p_y0, nbr, W1,
                                                (float*)p_y1, g1, b1, N, invN); // 5 (profiled)
    fuse_h_kernel<<<(N + 15) / 16, 256>>>((const float*)p_y1, g1, b1, seg, N, invN); // 6
    out_kernel<<<(U + 31) / 32, 256>>>(Wf, bf, (float*)d_out, U);            // 7
}

// round 5
// speedup vs baseline: 1.5691x; 1.5691x over previous
#include <cuda_runtime.h>

#define CEPS 1e-3f

// scratch (allocation-free rule: __device__ globals)
__device__ float g_y0[100000 * 16];
__device__ float g_y1[100000 * 16];
__device__ float g_merged[200000 * 16];
__device__ float g_stats[64];   // [0:16) sum0, [16:32) sq0, [32:48) sum1, [48:64) sq1

// ---------------------------------------------------------------------------
// Submanifold 3x3x3 conv: y[n,o] = sum_k sum_c x[nbr[n,k],c] * W[k,c,o]
// Block: 256 threads -> 128 rows x 16 out-ch.  Thread: 8 rows x 1 ch.
// Neighbor table staged to SMEM (coalesced). Gather tile + W slice are
// double-buffered: stage k+1 while computing k, one sync per k.
// LAYER==1 computes the layer-0 BN affine from g_stats in the prologue and
// applies BN+ReLU to gathered values on the fly (missing neighbors stay 0).
// ---------------------------------------------------------------------------
template <int LAYER>
__global__ __launch_bounds__(256) void conv_kernel(
    const float* __restrict__ x, const int* __restrict__ nbr,
    const float* __restrict__ W, float* __restrict__ y,
    const float* __restrict__ g, const float* __restrict__ b,
    int N, float invN)
{
    __shared__ int   snbr[128 * 27];      // 13.8 KB
    __shared__ float xs[2][16 * 132];     // 16.9 KB, transposed [c][row]
    __shared__ float wk[2][256];          //  2.0 KB, per-k [c][o]
    __shared__ float saff[32];

    int tid = threadIdx.x;
    int row0 = blockIdx.x * 128;

    // stage neighbor table, coalesced
    int lim = (N - row0) * 27;
    for (int i = tid; i < 128 * 27; i += 256)
        snbr[i] = (i < lim) ? nbr[row0 * 27 + i] : -1;

    if (LAYER == 1 && tid < 16) {
        float mu  = g_stats[tid] * invN;
        float var = g_stats[16 + tid] * invN - mu * mu;
        float s   = g[tid] * rsqrtf(var + CEPS);
        saff[tid]      = s;
        saff[16 + tid] = b[tid] - mu * s;
    }

    int tx = tid & 15;    // output channel
    int ty = tid >> 4;    // row group (8 rows)

    float acc[8];
#pragma unroll
    for (int j = 0; j < 8; j++) acc[j] = 0.f;

    __syncthreads();

    auto stage = [&](int k, int buf) {
        wk[buf][tid] = W[k * 256 + tid];
#pragma unroll
        for (int i = 0; i < 2; i++) {
            int e  = tid + i * 256;     // 0..511 -> (row, c-quad)
            int r  = e >> 2;            // 0..127
            int c4 = (e & 3) * 4;
            int id = snbr[r * 27 + k];
            float4 v = make_float4(0.f, 0.f, 0.f, 0.f);
            if (id >= 0) {
                v = *(const float4*)(x + id * 16 + c4);
                if (LAYER == 1) {
                    v.x = fmaxf(fmaf(v.x, saff[c4 + 0], saff[16 + c4 + 0]), 0.f);
                    v.y = fmaxf(fmaf(v.y, saff[c4 + 1], saff[16 + c4 + 1]), 0.f);
                    v.z = fmaxf(fmaf(v.z, saff[c4 + 2], saff[16 + c4 + 2]), 0.f);
                    v.w = fmaxf(fmaf(v.w, saff[c4 + 3], saff[16 + c4 + 3]), 0.f);
                }
            }
            xs[buf][(c4 + 0) * 132 + r] = v.x;
            xs[buf][(c4 + 1) * 132 + r] = v.y;
            xs[buf][(c4 + 2) * 132 + r] = v.z;
            xs[buf][(c4 + 3) * 132 + r] = v.w;
        }
    };

    stage(0, 0);
    __syncthreads();

    for (int k = 0; k < 27; k++) {
        int cur = k & 1;
        if (k < 26) stage(k + 1, cur ^ 1);

        const float* wkc = wk[cur] + tx;
#pragma unroll
        for (int c = 0; c < 16; c++) {
            float wv = wkc[c * 16];
            const float* xc = xs[cur] + c * 132 + ty * 8;
            float4 xa = *(const float4*)(xc);
            float4 xb = *(const float4*)(xc + 4);
            acc[0] = fmaf(xa.x, wv, acc[0]);
            acc[1] = fmaf(xa.y, wv, acc[1]);
            acc[2] = fmaf(xa.z, wv, acc[2]);
            acc[3] = fmaf(xa.w, wv, acc[3]);
            acc[4] = fmaf(xb.x, wv, acc[4]);
            acc[5] = fmaf(xb.y, wv, acc[5]);
            acc[6] = fmaf(xb.z, wv, acc[6]);
            acc[7] = fmaf(xb.w, wv, acc[7]);
        }
        __syncthreads();
    }

    // ---- write y + BN statistics ----
    float ps = 0.f, pq = 0.f;
#pragma unroll
    for (int j = 0; j < 8; j++) {
        int gr = row0 + ty * 8 + j;
        if (gr < N) {
            y[gr * 16 + tx] = acc[j];
            ps += acc[j];
            pq += acc[j] * acc[j];
        }
    }
    float* red = xs[0];
    red[ty * 16 + tx] = ps;
    red[256 + ty * 16 + tx] = pq;
    __syncthreads();
    if (ty == 0) {
        float s = 0.f, q = 0.f;
#pragma unroll
        for (int j = 0; j < 16; j++) {
            s += red[j * 16 + tx];
            q += red[256 + j * 16 + tx];
        }
        int base = (LAYER == 0) ? 0 : 32;
        atomicAdd(&g_stats[base + tx], s);
        atomicAdd(&g_stats[base + 16 + tx], q);
    }
}

// tiny stats-zero kernel (keeps launch indices deterministic for ncu)
__global__ void zero_stats_kernel() {
    if (threadIdx.x < 64) g_stats[threadIdx.x] = 0.f;
}

// t2 = f2 @ Wobo + bobo, atomicAdd-scatter into merged (runs before convs)
__global__ __launch_bounds__(256) void fuse_t2_kernel(
    const float* __restrict__ f2, const float* __restrict__ Wobo,
    const float* __restrict__ bobo, const int* __restrict__ seg2, int N)
{
    __shared__ float Wo[256];
    __shared__ float sf[16 * 17];
    __shared__ float sb[16];
    int tid = threadIdx.x;
    Wo[tid] = Wobo[tid];
    if (tid < 16) sb[tid] = bobo[tid];
    int n0 = blockIdx.x * 16;
    if (tid < 64) {
        int r = tid >> 2, c4 = (tid & 3) * 4;
        float4 v = make_float4(0.f, 0.f, 0.f, 0.f);
        if (n0 + r < N) v = *(const float4*)(f2 + (n0 + r) * 16 + c4);
        sf[r * 17 + c4 + 0] = v.x; sf[r * 17 + c4 + 1] = v.y;
        sf[r * 17 + c4 + 2] = v.z; sf[r * 17 + c4 + 3] = v.w;
    }
    __syncthreads();
    int tx = tid & 15, ty = tid >> 4;
    int n = n0 + ty;
    if (n >= N) return;
    float acc = sb[tx];
#pragma unroll
    for (int c = 0; c < 16; c++)
        acc = fmaf(sf[ty * 17 + c], Wo[c * 16 + tx], acc);
    atomicAdd(&g_merged[seg2[n] * 16 + tx], acc);
}

// h = relu(bn1(y1)), atomicAdd-scatter into merged
__global__ __launch_bounds__(256) void fuse_h_kernel(
    const float* __restrict__ y1, const float* __restrict__ g1,
    const float* __restrict__ b1, const int* __restrict__ seg, int N, float invN)
{
    __shared__ float saff[32];
    int tid = threadIdx.x;
    if (tid < 16) {
        float mu  = g_stats[32 + tid] * invN;
        float var = g_stats[48 + tid] * invN - mu * mu;
        float s   = g1[tid] * rsqrtf(var + CEPS);
        saff[tid]      = s;
        saff[16 + tid] = b1[tid] - mu * s;
    }
    __syncthreads();
    int tx = tid & 15, ty = tid >> 4;
    int n = blockIdx.x * 16 + ty;
    if (n >= N) return;
    float h = fmaxf(fmaf(y1[n * 16 + tx], saff[tx], saff[16 + tx]), 0.f);
    atomicAdd(&g_merged[seg[n] * 16 + tx], h);
}

// out[u,:] = merged[u,:] @ Wf + bf.
// Block: 256 threads -> 32 rows x 128 cols. Warp = 4 rows (row idx warp-
// uniform -> x reads are pure SMEM broadcast; W reads LDS.128 conflict-free).
__global__ __launch_bounds__(256) void out_kernel(
    const float* __restrict__ Wf, const float* __restrict__ bf,
    float* __restrict__ out, int U)
{
    __shared__ float Wfs[2048];
    __shared__ float sx[32 * 16];
    int tid = threadIdx.x;
    for (int i = tid; i < 2048; i += 256) Wfs[i] = Wf[i];
    int u0 = blockIdx.x * 32;
    if (tid < 128) {
        int r = tid >> 2, c4 = (tid & 3) * 4;
        float4 v = make_float4(0.f, 0.f, 0.f, 0.f);
        if (u0 + r < U) v = *(const float4*)(g_merged + (u0 + r) * 16 + c4);
        *(float4*)(sx + r * 16 + c4) = v;
    }
    __syncthreads();

    int cx = tid & 31;      // col quad (cols cx*4 .. cx*4+3)
    int ry = tid >> 5;      // warp id -> rows ry*4 .. ry*4+3
    float4 bv = *(const float4*)(bf + cx * 4);
    float4 a0 = bv, a1 = bv, a2 = bv, a3 = bv;

#pragma unroll
    for (int c = 0; c < 16; c++) {
        float4 wv = *(const float4*)(Wfs + c * 128 + cx * 4);
        float x0 = sx[(ry * 4 + 0) * 16 + c];
        float x1 = sx[(ry * 4 + 1) * 16 + c];
        float x2 = sx[(ry * 4 + 2) * 16 + c];
        float x3 = sx[(ry * 4 + 3) * 16 + c];
        a0.x = fmaf(x0, wv.x, a0.x); a0.y = fmaf(x0, wv.y, a0.y);
        a0.z = fmaf(x0, wv.z, a0.z); a0.w = fmaf(x0, wv.w, a0.w);
        a1.x = fmaf(x1, wv.x, a1.x); a1.y = fmaf(x1, wv.y, a1.y);
        a1.z = fmaf(x1, wv.z, a1.z); a1.w = fmaf(x1, wv.w, a1.w);
        a2.x = fmaf(x2, wv.x, a2.x); a2.y = fmaf(x2, wv.y, a2.y);
        a2.z = fmaf(x2, wv.z, a2.z); a2.w = fmaf(x2, wv.w, a2.w);
        a3.x = fmaf(x3, wv.x, a3.x); a3.y = fmaf(x3, wv.y, a3.y);
        a3.z = fmaf(x3, wv.z, a3.z); a3.w = fmaf(x3, wv.w, a3.w);
    }

    int u = u0 + ry * 4;
    if (u + 0 < U) *(float4*)(out + (u + 0) * 128 + cx * 4) = a0;
    if (u + 1 < U) *(float4*)(out + (u + 1) * 128 + cx * 4) = a1;
    if (u + 2 < U) *(float4*)(out + (u + 2) * 128 + cx * 4) = a2;
    if (u + 3 < U) *(float4*)(out + (u + 3) * 128 + cx * 4) = a3;
}

extern "C" void kernel_launch(void* const* d_in, const int* in_sizes, int n_in,
                              void* d_out, int out_size)
{
    const float* vox  = (const float*)d_in[0];
    const float* f2   = (const float*)d_in[1];
    const float* W0   = (const float*)d_in[2];
    const float* g0   = (const float*)d_in[3];
    const float* b0   = (const float*)d_in[4];
    const float* W1   = (const float*)d_in[5];
    const float* g1   = (const float*)d_in[6];
    const float* b1   = (const float*)d_in[7];
    const float* Wobo = (const float*)d_in[8];
    const float* bobo = (const float*)d_in[9];
    const float* Wf   = (const float*)d_in[10];
    const float* bf   = (const float*)d_in[11];
    const int*   nbr  = (const int*)d_in[12];
    const int*   seg  = (const int*)d_in[13];

    int N = in_sizes[0] / 16;
    int U = out_size / 128;

    void *p_merged, *p_y0, *p_y1;
    cudaGetSymbolAddress(&p_merged, g_merged);
    cudaGetSymbolAddress(&p_y0,     g_y0);
    cudaGetSymbolAddress(&p_y1,     g_y1);

    size_t mbytes = (size_t)U * 16 * sizeof(float);
    size_t mhalf  = (mbytes / 2) & ~(size_t)255;
    float invN = 1.0f / (float)N;
    int cblocks = (N + 127) / 128;

    // launch indices (ncu -s 5 -c 1 profiles index 5 = conv1)
    cudaMemsetAsync(p_merged, 0, mhalf);                                      // 0
    cudaMemsetAsync((char*)p_merged + mhalf, 0, mbytes - mhalf);              // 1
    zero_stats_kernel<<<1, 64>>>();                                           // 2
    fuse_t2_kernel<<<(N + 15) / 16, 256>>>(f2, Wobo, bobo, seg + N, N);       // 3
    conv_kernel<0><<<cblocks, 256>>>(vox, nbr, W0, (float*)p_y0,
                                     g0, b0, N, invN);                        // 4
    conv_kernel<1><<<cblocks, 256>>>((const float*)p_y0, nbr, W1,
                                     (float*)p_y1, g1, b1, N, invN);          // 5 (profiled)
    fuse_h_kernel<<<(N + 15) / 16, 256>>>((const float*)p_y1, g1, b1,
                                          seg, N, invN);                      // 6
    out_kernel<<<(U + 31) / 32, 256>>>(Wf, bf, (float*)d_out, U);             // 7
}